// round 16
// baseline (speedup 1.0000x reference)
#include <cuda_runtime.h>
#include <cuda_fp16.h>

#define NQ    20000
#define NA    100000
#define KNN   32
#define HID   128
#define E_F   16

#define KVB   1563              // (NA+63)/64  KV row-blocks of 64
#define QBL   157               // (NQ+127)/128 Q row-blocks of 128
#define KVC   270               // persistent CTAs for KV
#define QC    26                // persistent CTAs for Q
#define MLPB  157

// ---------------- scratch (static device globals; no runtime alloc) ----------
__device__ __align__(16) float  g_Qq [NQ * HID];
__device__ __align__(16) __half g_Ka [NA * HID];
__device__ __align__(16) __half g_Va [NA * HID];
__device__ __align__(16) unsigned g_W1f[16384];   // W1 frags: 64KB
__device__ __align__(16) unsigned g_W2f[8192];    // W2 frags: 32KB
__device__ __align__(16) float  g_agg[NQ * HID];

// ------------------------- fp16 MMA helpers ----------------------------------
__device__ __forceinline__ unsigned ph2(float x, float y) {
    __half2 h = __floats2half2_rn(x, y);
    return *reinterpret_cast<unsigned*>(&h);
}
__device__ __forceinline__ void mma16(float* d, unsigned a0, unsigned a1,
                                      unsigned a2, unsigned a3,
                                      unsigned b0, unsigned b1) {
    asm volatile(
        "mma.sync.aligned.m16n8k16.row.col.f32.f16.f16.f32 "
        "{%0,%1,%2,%3}, {%4,%5,%6,%7}, {%8,%9}, {%0,%1,%2,%3};"
        : "+f"(d[0]), "+f"(d[1]), "+f"(d[2]), "+f"(d[3])
        : "r"(a0), "r"(a1), "r"(a2), "r"(a3), "r"(b0), "r"(b1));
}

// Fragment storage (uint2 per (chunk,row,tig)): idx = (chunk*ROWS + row)*4 + tig
__device__ __forceinline__ void pack_frags(
    const float* __restrict__ S, unsigned* U, int rowbase, int rows,
    int maxrow, int stride, int lgNC, int tid, int nthr)
{
    const int NC = 1 << lgNC;
    const int total = rows * NC * 4;
    for (int idx = tid; idx < total; idx += nthr) {
        const int tig    = idx & 3;
        const int rlo    = (idx >> 2) & 7;
        const int rest   = idx >> 5;
        const int chunk  = rest & (NC - 1);
        const int rblock = rest >> lgNC;
        const int row    = rblock * 8 + rlo;
        const int gr     = rowbase + row;
        float2 f0 = make_float2(0.f, 0.f), f1 = f0;
        if (gr < maxrow) {
            const float* p = S + (size_t)gr * stride + chunk * 16 + tig * 2;
            f0 = *(const float2*)p;
            f1 = *(const float2*)(p + 8);
        }
        uint2 v;
        v.x = ph2(f0.x, f0.y);
        v.y = ph2(f1.x, f1.y);
        ((uint2*)U)[(chunk * rows + row) * 4 + tig] = v;
    }
}

// 16x64 warp-tile GEMM over 8 k16 chunks.
__device__ __forceinline__ void gemm_frag(const uint2* __restrict__ AF, int AR,
                                          const uint2* __restrict__ WF, int wcoff,
                                          float d[8][4], int mrow, int colh,
                                          int g, int tig) {
#pragma unroll
    for (int c = 0; c < 8; c++) {
        const uint2 aA = AF[(c * AR + mrow + g) * 4 + tig];
        const uint2 aB = AF[(c * AR + mrow + 8 + g) * 4 + tig];
#pragma unroll
        for (int nt = 0; nt < 8; nt++) {
            const int n = colh * 64 + nt * 8 + g;
            const uint2 b = WF[((wcoff + c) * 128 + n) * 4 + tig];
            mma16(d[nt], aA.x, aB.x, aA.y, aB.y, b.x, b.y);
        }
    }
}

// ---------------------------------------------------------------------------
// proj_all (unchanged R15): 296 persistent CTAs + 2 prepack blocks.
// ---------------------------------------------------------------------------
__global__ __launch_bounds__(512, 2) void proj_all(
    const float* __restrict__ hA, const float* __restrict__ hQ,
    const float* __restrict__ Wk, const float* __restrict__ Wv,
    const float* __restrict__ Wq,
    const float* __restrict__ W1, const float* __restrict__ W2,
    unsigned* __restrict__ W1f, unsigned* __restrict__ W2f,
    __half* __restrict__ Ck, __half* __restrict__ Cv, float* __restrict__ Cq)
{
    extern __shared__ unsigned U[];
    const int tid  = threadIdx.x;
    const int warp = tid >> 5;
    const int lane = tid & 31;
    const int g    = lane >> 2;
    const int tig  = lane & 3;

    if (blockIdx.x >= KVC + QC) {
        if (blockIdx.x == KVC + QC)
            pack_frags(W1, W1f, 0, 128, 1 << 30, 256, 4, tid, 512);
        else
            pack_frags(W2, W2f, 0, 128, 1 << 30, HID, 3, tid, 512);
        return;
    }

    if (blockIdx.x < KVC) {
        pack_frags(Wk, U,        0, 128, 1 << 30, HID, 3, tid, 512);
        pack_frags(Wv, U + 8192, 0, 128, 1 << 30, HID, 3, tid, 512);
        __syncthreads();

        const int gid  = warp >> 2;
        const int sel  = (warp >> 1) & 1;
        const int colh = warp & 1;
        const int gt   = tid & 127;
        __half* Cp = sel ? Cv : Ck;

        unsigned* Abase = U + 16384 + gid * 2048;

        auto decode = [&](int e, int& row, int& smi, int& gof) {
            const int idx  = gt + e * 128;
            const int tg   = idx & 3;
            const int rlo  = (idx >> 2) & 7;
            const int rest = idx >> 5;
            const int chk  = rest & 7;
            row = (rest >> 3) * 8 + rlo;
            smi = (chk * 16 + row) * 4 + tg;
            gof = row * HID + chk * 16 + tg * 2;
        };

        int blk = blockIdx.x;
        {
            const int srow = blk * 64 + gid * 16;
#pragma unroll
            for (int e = 0; e < 4; e++) {
                int row, smi, gof;
                decode(e, row, smi, gof);
                uint2 v = make_uint2(0u, 0u);
                if (srow + row < NA) {
                    const float* p = hA + (size_t)srow * HID + gof;
                    const float2 f0 = *(const float2*)p;
                    const float2 f1 = *(const float2*)(p + 8);
                    v.x = ph2(f0.x, f0.y);
                    v.y = ph2(f1.x, f1.y);
                }
                ((uint2*)Abase)[smi] = v;
            }
        }
        asm volatile("bar.sync %0, 128;" :: "r"(1 + gid) : "memory");

        int cur = 0;
        while (blk < KVB) {
            const int nxt = blk + KVC;
            uint2 stg[4];
            if (nxt < KVB) {
                const int srow = nxt * 64 + gid * 16;
#pragma unroll
                for (int e = 0; e < 4; e++) {
                    int row, smi, gof;
                    decode(e, row, smi, gof);
                    stg[e] = make_uint2(0u, 0u);
                    if (srow + row < NA) {
                        const float* p = hA + (size_t)srow * HID + gof;
                        const float2 f0 = *(const float2*)p;
                        const float2 f1 = *(const float2*)(p + 8);
                        stg[e].x = ph2(f0.x, f0.y);
                        stg[e].y = ph2(f1.x, f1.y);
                    }
                }
            }

            float d[8][4];
#pragma unroll
            for (int i = 0; i < 8; i++)
#pragma unroll
                for (int j = 0; j < 4; j++) d[i][j] = 0.f;

            gemm_frag((const uint2*)(Abase + cur * 1024), 16,
                      (const uint2*)(U + sel * 8192), 0, d, 0, colh, g, tig);

            const int brow = blk * 64 + gid * 16;
#pragma unroll
            for (int half = 0; half < 2; half++) {
                const int row = brow + g + half * 8;
                if (row < NA) {
#pragma unroll
                    for (int nt = 0; nt < 8; nt++) {
                        const int col = colh * 64 + nt * 8 + 2 * tig;
                        *(unsigned*)&Cp[(size_t)row * HID + col] =
                            ph2(d[nt][half * 2 + 0], d[nt][half * 2 + 1]);
                    }
                }
            }

            if (nxt < KVB) {
                unsigned* A1 = Abase + (cur ^ 1) * 1024;
#pragma unroll
                for (int e = 0; e < 4; e++) {
                    int row, smi, gof;
                    decode(e, row, smi, gof);
                    ((uint2*)A1)[smi] = stg[e];
                }
            }
            asm volatile("bar.sync %0, 128;" :: "r"(1 + gid) : "memory");
            blk = nxt;
            cur ^= 1;
        }
    } else {
        pack_frags(Wq, U, 0, 128, 1 << 30, HID, 3, tid, 512);

        const int mrow = (warp >> 1) * 16;
        const int colh = warp & 1;

        for (int blk = (int)blockIdx.x - KVC; blk < QBL; blk += QC) {
            const int brow = blk * 128;
            pack_frags(hQ, U + 8192, brow, 128, NQ, HID, 3, tid, 512);
            __syncthreads();

            float d[8][4];
#pragma unroll
            for (int i = 0; i < 8; i++)
#pragma unroll
                for (int j = 0; j < 4; j++) d[i][j] = 0.f;

            gemm_frag((const uint2*)(U + 8192), 128,
                      (const uint2*)U, 0, d, mrow, colh, g, tig);

#pragma unroll
            for (int half = 0; half < 2; half++) {
                const int row = brow + mrow + g + half * 8;
                if (row >= NQ) continue;
#pragma unroll
                for (int nt = 0; nt < 8; nt++) {
                    const int col = colh * 64 + nt * 8 + 2 * tig;
                    *(float2*)&Cq[(size_t)row * HID + col] =
                        make_float2(d[nt][half * 2 + 0], d[nt][half * 2 + 1]);
                }
            }
            __syncthreads();
        }
    }
}

// ---------------------------------------------------------------------------
// mlp_fused (unchanged R15: prepacked-weight copies)
// ---------------------------------------------------------------------------
__global__ __launch_bounds__(512, 2) void mlp_fused(
    const float* __restrict__ hQ, const float* __restrict__ agg,
    const unsigned* __restrict__ W1f, const float* __restrict__ b1,
    const unsigned* __restrict__ W2f, const float* __restrict__ b2,
    const float* __restrict__ gamma, const float* __restrict__ beta,
    float* __restrict__ out)
{
    extern __shared__ unsigned U[];
    __shared__ float2 scr[256];
    unsigned* AU = U + 16384;

    const int tid  = threadIdx.x;
    const int warp = tid >> 5;
    const int lane = tid & 31;
    const int g    = lane >> 2;
    const int tig  = lane & 3;
    const int mrow = (warp >> 1) * 16;
    const int colh = warp & 1;
    const int brow = blockIdx.x * 128;

    float d[8][4];
#pragma unroll
    for (int i = 0; i < 8; i++)
#pragma unroll
        for (int j = 0; j < 4; j++) d[i][j] = 0.f;

    {
        const uint4* src = (const uint4*)W1f;
        uint4* dst = (uint4*)U;
#pragma unroll
        for (int i = 0; i < 8; i++) dst[tid + i * 512] = src[tid + i * 512];
    }
    pack_frags(hQ, AU, brow, 128, NQ, HID, 3, tid, 512);
    __syncthreads();
    gemm_frag((const uint2*)AU, 128, (const uint2*)U, 0, d, mrow, colh, g, tig);
    __syncthreads();
    pack_frags(agg, AU, brow, 128, NQ, HID, 3, tid, 512);
    __syncthreads();
    gemm_frag((const uint2*)AU, 128, (const uint2*)U, 8, d, mrow, colh, g, tig);
    __syncthreads();

#pragma unroll
    for (int half = 0; half < 2; half++) {
        const int rl = mrow + g + half * 8;
#pragma unroll
        for (int nt = 0; nt < 8; nt++) {
            const int col = colh * 64 + nt * 8 + 2 * tig;
            const float2 bi = *(const float2*)&b1[col];
            const float x0 = fmaxf(d[nt][half * 2 + 0] + bi.x, 0.f);
            const float x1 = fmaxf(d[nt][half * 2 + 1] + bi.y, 0.f);
            const int chunk = colh * 4 + (nt >> 1);
            AU[((chunk * 128 + rl) * 4 + tig) * 2 + (nt & 1)] = ph2(x0, x1);
        }
    }
    {
        const uint4* src = (const uint4*)W2f;
        uint4* dst = (uint4*)U;
#pragma unroll
        for (int i = 0; i < 4; i++) dst[tid + i * 512] = src[tid + i * 512];
    }
    __syncthreads();

#pragma unroll
    for (int i = 0; i < 8; i++)
#pragma unroll
        for (int j = 0; j < 4; j++) d[i][j] = 0.f;
    gemm_frag((const uint2*)AU, 128, (const uint2*)U, 0, d, mrow, colh, g, tig);

    float psum[2], psq[2];
#pragma unroll
    for (int half = 0; half < 2; half++) {
        const int  row = brow + mrow + g + half * 8;
        const bool ok  = row < NQ;
        float s = 0.f, ss = 0.f;
#pragma unroll
        for (int nt = 0; nt < 8; nt++) {
            const int col = colh * 64 + nt * 8 + 2 * tig;
            const float2 bi = *(const float2*)&b2[col];
            float x0 = d[nt][half * 2 + 0] + bi.x;
            float x1 = d[nt][half * 2 + 1] + bi.y;
            if (ok) {
                const float2 rr = *(const float2*)&hQ[(size_t)row * HID + col];
                x0 += rr.x; x1 += rr.y;
            }
            d[nt][half * 2 + 0] = x0;
            d[nt][half * 2 + 1] = x1;
            s  += x0 + x1;
            ss += x0 * x0 + x1 * x1;
        }
        s  += __shfl_xor_sync(0xffffffffu, s, 1);
        s  += __shfl_xor_sync(0xffffffffu, s, 2);
        ss += __shfl_xor_sync(0xffffffffu, ss, 1);
        ss += __shfl_xor_sync(0xffffffffu, ss, 2);
        psum[half] = s; psq[half] = ss;
    }
#pragma unroll
    for (int half = 0; half < 2; half++) {
        const int rl = mrow + g + half * 8;
        if (tig == 0) scr[rl * 2 + colh] = make_float2(psum[half], psq[half]);
    }
    __syncthreads();
#pragma unroll
    for (int half = 0; half < 2; half++) {
        const int rl  = mrow + g + half * 8;
        const int row = brow + rl;
        const float2 f0 = scr[rl * 2 + 0];
        const float2 f1 = scr[rl * 2 + 1];
        const float mean = (f0.x + f1.x) * (1.f / 128.f);
        const float inv  = rsqrtf((f0.y + f1.y) * (1.f / 128.f)
                                  - mean * mean + 1e-5f);
        if (row >= NQ) continue;
#pragma unroll
        for (int nt = 0; nt < 8; nt++) {
            const int col = colh * 64 + nt * 8 + 2 * tig;
            const float2 gg = *(const float2*)&gamma[col];
            const float2 bb = *(const float2*)&beta[col];
            float2 o;
            o.x = (d[nt][half * 2 + 0] - mean) * inv * gg.x + bb.x;
            o.y = (d[nt][half * 2 + 1] - mean) * inv * gg.y + bb.y;
            *(float2*)&out[(size_t)row * HID + col] = o;
        }
    }
}

// ---------------------------------------------------------------------------
// Attention v3: TWO warps per query (pair pw=0/1 owns edges [16pw,16pw+16)).
// Halves serial score/V-agg depth, doubles per-query MLP. Cross-warp combine
// via smem + bar.sync(1+qp, 64). 4 queries per 256-thread CTA.
// ---------------------------------------------------------------------------
__global__ __launch_bounds__(256) void attn_kernel(
    const float* __restrict__ Qq, const __half* __restrict__ Ka,
    const __half* __restrict__ Va, const float* __restrict__ edge_attr,
    const int*   __restrict__ src_idx, const float* __restrict__ W_rbf,
    float* __restrict__ agg)
{
    __shared__ int    s_src[4][32];
    __shared__ float4 s_ea[4][128];
    __shared__ float  s_m[4][2][8];
    __shared__ float  s_s[4][2][8];
    __shared__ float  s_al[4][8 * 36];
    __shared__ float  s_vp[4][128];

    const int warp  = threadIdx.x >> 5;
    const int lane  = threadIdx.x & 31;
    const int qp    = warp >> 1;
    const int pw    = warp & 1;
    const int q     = blockIdx.x * 4 + qp;
    const int h     = lane >> 2;
    const int sm4   = lane & 3;
    const int barid = 1 + qp;

    // staging (split across the pair)
    if (pw == 0) s_src[qp][lane] = src_idx[(size_t)q * KNN + lane];
    {
        const float4* ea4 = (const float4*)(edge_attr + (size_t)q * KNN * E_F);
        s_ea[qp][lane + 32 * pw]       = ea4[lane + 32 * pw];
        s_ea[qp][lane + 32 * (2 + pw)] = ea4[lane + 32 * (2 + pw)];
    }

    float qv[16], wr[16];
    {
        const float4* qp_ = (const float4*)(Qq + (size_t)q * HID + h * 16);
        const float4* wp  = (const float4*)(W_rbf + h * E_F);
#pragma unroll
        for (int i = 0; i < 4; i++) {
            float4 a = qp_[i];
            qv[i * 4 + 0] = a.x; qv[i * 4 + 1] = a.y;
            qv[i * 4 + 2] = a.z; qv[i * 4 + 3] = a.w;
            float4 b = wp[i];
            wr[i * 4 + 0] = b.x; wr[i * 4 + 1] = b.y;
            wr[i * 4 + 2] = b.z; wr[i * 4 + 3] = b.w;
        }
    }
    asm volatile("bar.sync %0, 64;" :: "r"(barid) : "memory");

    // scores of my 4 edges (no shuffles)
    float sc[4];
#pragma unroll
    for (int t = 0; t < 4; t++) {
        const int j  = pw * 16 + sm4 + 4 * t;
        const int sj = s_src[qp][j];
        const uint4 k0 = *(const uint4*)(Ka + (size_t)sj * HID + h * 16);
        const uint4 k1 = *(const uint4*)(Ka + (size_t)sj * HID + h * 16 + 8);
        float dd = 0.f;
        const __half2* kh = (const __half2*)&k0;
#pragma unroll
        for (int i = 0; i < 4; i++) {
            const float2 f = __half22float2(kh[i]);
            dd = fmaf(qv[i * 2 + 0], f.x, dd);
            dd = fmaf(qv[i * 2 + 1], f.y, dd);
        }
        const __half2* kh1 = (const __half2*)&k1;
#pragma unroll
        for (int i = 0; i < 4; i++) {
            const float2 f = __half22float2(kh1[i]);
            dd = fmaf(qv[8 + i * 2 + 0], f.x, dd);
            dd = fmaf(qv[8 + i * 2 + 1], f.y, dd);
        }
        float rr = 0.f;
#pragma unroll
        for (int c = 0; c < 4; c++) {
            const float4 e = s_ea[qp][j * 4 + c];
            rr = fmaf(e.x, wr[c * 4 + 0], rr);
            rr = fmaf(e.y, wr[c * 4 + 1], rr);
            rr = fmaf(e.z, wr[c * 4 + 2], rr);
            rr = fmaf(e.w, wr[c * 4 + 3], rr);
        }
        sc[t] = dd * 0.25f + rr;
    }

    // softmax: warp-half max -> combine -> exp/sum -> combine
    float m = sc[0];
#pragma unroll
    for (int t = 1; t < 4; t++) m = fmaxf(m, sc[t]);
    m = fmaxf(m, __shfl_xor_sync(0xffffffffu, m, 1));
    m = fmaxf(m, __shfl_xor_sync(0xffffffffu, m, 2));
    if (sm4 == 0) s_m[qp][pw][h] = m;
    asm volatile("bar.sync %0, 64;" :: "r"(barid) : "memory");
    m = fmaxf(s_m[qp][0][h], s_m[qp][1][h]);

    float sum = 0.f;
#pragma unroll
    for (int t = 0; t < 4; t++) { sc[t] = __expf(sc[t] - m); sum += sc[t]; }
    sum += __shfl_xor_sync(0xffffffffu, sum, 1);
    sum += __shfl_xor_sync(0xffffffffu, sum, 2);
    if (sm4 == 0) s_s[qp][pw][h] = sum;
    asm volatile("bar.sync %0, 64;" :: "r"(barid) : "memory");
    const float inv = 1.f / (s_s[qp][0][h] + s_s[qp][1][h] + 1e-16f);
#pragma unroll
    for (int t = 0; t < 4; t++)
        s_al[qp][h * 36 + pw * 16 + sm4 + 4 * t] = sc[t] * inv;
    asm volatile("bar.sync %0, 64;" :: "r"(barid) : "memory");

    // V aggregation over my 16 edges; lane covers dims [4*lane, +4)
    float4 acc = make_float4(0.f, 0.f, 0.f, 0.f);
#pragma unroll
    for (int jj = 0; jj < 16; jj++) {
        const int j  = pw * 16 + jj;
        const float a  = s_al[qp][h * 36 + j];
        const int   sj = s_src[qp][j];
        const __half2* vr = (const __half2*)(Va + (size_t)sj * HID);
        const float2 v01 = __half22float2(vr[lane * 2 + 0]);
        const float2 v23 = __half22float2(vr[lane * 2 + 1]);
        acc.x = fmaf(a, v01.x, acc.x);
        acc.y = fmaf(a, v01.y, acc.y);
        acc.z = fmaf(a, v23.x, acc.z);
        acc.w = fmaf(a, v23.y, acc.w);
    }
    if (pw == 1) *(float4*)&s_vp[qp][lane * 4] = acc;
    asm volatile("bar.sync %0, 64;" :: "r"(barid) : "memory");
    if (pw == 0) {
        const float4 o = *(const float4*)&s_vp[qp][lane * 4];
        acc.x += o.x; acc.y += o.y; acc.z += o.z; acc.w += o.w;
        *(float4*)&agg[(size_t)q * HID + lane * 4] = acc;
    }
}

// ---------------------------------------------------------------------------
extern "C" void kernel_launch(void* const* d_in, const int* in_sizes, int n_in,
                              void* d_out, int out_size)
{
    const float* h_atom    = (const float*)d_in[0];
    const float* h_query   = (const float*)d_in[1];
    const float* edge_attr = (const float*)d_in[2];
    const float* W_q       = (const float*)d_in[3];
    const float* W_k       = (const float*)d_in[4];
    const float* W_v       = (const float*)d_in[5];
    const float* W_rbf     = (const float*)d_in[6];
    const float* W1        = (const float*)d_in[7];
    const float* b1        = (const float*)d_in[8];
    const float* W2        = (const float*)d_in[9];
    const float* b2        = (const float*)d_in[10];
    const float* ln_gamma  = (const float*)d_in[11];
    const float* ln_beta   = (const float*)d_in[12];
    const int*   edge_index= (const int*)  d_in[13];   // [2,E]; row0 = src
    float* out = (float*)d_out;

    float *Qq, *agg;
    __half *Ka, *Va;
    unsigned *W1f, *W2f;
    cudaGetSymbolAddress((void**)&Qq,  g_Qq);
    cudaGetSymbolAddress((void**)&Ka,  g_Ka);
    cudaGetSymbolAddress((void**)&Va,  g_Va);
    cudaGetSymbolAddress((void**)&agg, g_agg);
    cudaGetSymbolAddress((void**)&W1f, g_W1f);
    cudaGetSymbolAddress((void**)&W2f, g_W2f);

    cudaFuncSetAttribute(proj_all,
                         cudaFuncAttributeMaxDynamicSharedMemorySize, 98304);
    cudaFuncSetAttribute(mlp_fused,
                         cudaFuncAttributeMaxDynamicSharedMemorySize, 98304);

    // persistent Q+K+V projections + W1/W2 fragment prepack (2 extra blocks)
    proj_all<<<KVC + QC + 2, 512, 98304>>>(h_atom, h_query, W_k, W_v, W_q,
                                           W1, W2, W1f, W2f, Ka, Va, Qq);

    // segment-softmax attention + aggregation (2 warps per query)
    attn_kernel<<<NQ / 4, 256>>>(Qq, Ka, Va, edge_attr, edge_index, W_rbf, agg);

    // fused MLP1 + ReLU + MLP2 + residual + LayerNorm (prepacked weights)
    mlp_fused<<<MLPB, 512, 98304>>>(h_query, agg, W1f, b1, W2f, b2,
                                    ln_gamma, ln_beta, out);
}

// round 17
// speedup vs baseline: 1.0240x; 1.0240x over previous
#include <cuda_runtime.h>
#include <cuda_fp16.h>

#define NQ    20000
#define NA    100000
#define KNN   32
#define HID   128
#define E_F   16

#define KVB   1563              // (NA+63)/64  KV row-blocks of 64
#define QBL   157               // (NQ+127)/128 Q row-blocks of 128
#define KVC   270               // persistent CTAs for KV
#define QC    26                // persistent CTAs for Q
#define MLPB  157

// ---------------- scratch (static device globals; no runtime alloc) ----------
__device__ __align__(16) __half g_Qq [NQ * HID];
__device__ __align__(16) __half g_Ka [NA * HID];
__device__ __align__(16) __half g_Va [NA * HID];
__device__ __align__(16) unsigned g_W1f[16384];   // W1 frags: 64KB
__device__ __align__(16) unsigned g_W2f[8192];    // W2 frags: 32KB
__device__ __align__(16) float  g_agg[NQ * HID];

// ------------------------- fp16 MMA helpers ----------------------------------
__device__ __forceinline__ unsigned ph2(float x, float y) {
    __half2 h = __floats2half2_rn(x, y);
    return *reinterpret_cast<unsigned*>(&h);
}
__device__ __forceinline__ void mma16(float* d, unsigned a0, unsigned a1,
                                      unsigned a2, unsigned a3,
                                      unsigned b0, unsigned b1) {
    asm volatile(
        "mma.sync.aligned.m16n8k16.row.col.f32.f16.f16.f32 "
        "{%0,%1,%2,%3}, {%4,%5,%6,%7}, {%8,%9}, {%0,%1,%2,%3};"
        : "+f"(d[0]), "+f"(d[1]), "+f"(d[2]), "+f"(d[3])
        : "r"(a0), "r"(a1), "r"(a2), "r"(a3), "r"(b0), "r"(b1));
}

// Fragment storage (uint2 per (chunk,row,tig)): idx = (chunk*ROWS + row)*4 + tig
__device__ __forceinline__ void pack_frags(
    const float* __restrict__ S, unsigned* U, int rowbase, int rows,
    int maxrow, int stride, int lgNC, int tid, int nthr)
{
    const int NC = 1 << lgNC;
    const int total = rows * NC * 4;
    for (int idx = tid; idx < total; idx += nthr) {
        const int tig    = idx & 3;
        const int rlo    = (idx >> 2) & 7;
        const int rest   = idx >> 5;
        const int chunk  = rest & (NC - 1);
        const int rblock = rest >> lgNC;
        const int row    = rblock * 8 + rlo;
        const int gr     = rowbase + row;
        float2 f0 = make_float2(0.f, 0.f), f1 = f0;
        if (gr < maxrow) {
            const float* p = S + (size_t)gr * stride + chunk * 16 + tig * 2;
            f0 = *(const float2*)p;
            f1 = *(const float2*)(p + 8);
        }
        uint2 v;
        v.x = ph2(f0.x, f0.y);
        v.y = ph2(f1.x, f1.y);
        ((uint2*)U)[(chunk * rows + row) * 4 + tig] = v;
    }
}

// 16x64 warp-tile GEMM over 8 k16 chunks.
__device__ __forceinline__ void gemm_frag(const uint2* __restrict__ AF, int AR,
                                          const uint2* __restrict__ WF, int wcoff,
                                          float d[8][4], int mrow, int colh,
                                          int g, int tig) {
#pragma unroll
    for (int c = 0; c < 8; c++) {
        const uint2 aA = AF[(c * AR + mrow + g) * 4 + tig];
        const uint2 aB = AF[(c * AR + mrow + 8 + g) * 4 + tig];
#pragma unroll
        for (int nt = 0; nt < 8; nt++) {
            const int n = colh * 64 + nt * 8 + g;
            const uint2 b = WF[((wcoff + c) * 128 + n) * 4 + tig];
            mma16(d[nt], aA.x, aB.x, aA.y, aB.y, b.x, b.y);
        }
    }
}

// ---------------------------------------------------------------------------
// proj_all: 296 persistent CTAs + 2 prepack blocks, 512 threads, 2 CTAs/SM.
// Q output now fp16 (halves Q epilogue traffic).
// ---------------------------------------------------------------------------
__global__ __launch_bounds__(512, 2) void proj_all(
    const float* __restrict__ hA, const float* __restrict__ hQ,
    const float* __restrict__ Wk, const float* __restrict__ Wv,
    const float* __restrict__ Wq,
    const float* __restrict__ W1, const float* __restrict__ W2,
    unsigned* __restrict__ W1f, unsigned* __restrict__ W2f,
    __half* __restrict__ Ck, __half* __restrict__ Cv, __half* __restrict__ Cq)
{
    extern __shared__ unsigned U[];
    const int tid  = threadIdx.x;
    const int warp = tid >> 5;
    const int lane = tid & 31;
    const int g    = lane >> 2;
    const int tig  = lane & 3;

    if (blockIdx.x >= KVC + QC) {
        if (blockIdx.x == KVC + QC)
            pack_frags(W1, W1f, 0, 128, 1 << 30, 256, 4, tid, 512);
        else
            pack_frags(W2, W2f, 0, 128, 1 << 30, HID, 3, tid, 512);
        return;
    }

    if (blockIdx.x < KVC) {
        pack_frags(Wk, U,        0, 128, 1 << 30, HID, 3, tid, 512);
        pack_frags(Wv, U + 8192, 0, 128, 1 << 30, HID, 3, tid, 512);
        __syncthreads();

        const int gid  = warp >> 2;
        const int sel  = (warp >> 1) & 1;
        const int colh = warp & 1;
        const int gt   = tid & 127;
        __half* Cp = sel ? Cv : Ck;

        unsigned* Abase = U + 16384 + gid * 2048;

        auto decode = [&](int e, int& row, int& smi, int& gof) {
            const int idx  = gt + e * 128;
            const int tg   = idx & 3;
            const int rlo  = (idx >> 2) & 7;
            const int rest = idx >> 5;
            const int chk  = rest & 7;
            row = (rest >> 3) * 8 + rlo;
            smi = (chk * 16 + row) * 4 + tg;
            gof = row * HID + chk * 16 + tg * 2;
        };

        int blk = blockIdx.x;
        {
            const int srow = blk * 64 + gid * 16;
#pragma unroll
            for (int e = 0; e < 4; e++) {
                int row, smi, gof;
                decode(e, row, smi, gof);
                uint2 v = make_uint2(0u, 0u);
                if (srow + row < NA) {
                    const float* p = hA + (size_t)srow * HID + gof;
                    const float2 f0 = *(const float2*)p;
                    const float2 f1 = *(const float2*)(p + 8);
                    v.x = ph2(f0.x, f0.y);
                    v.y = ph2(f1.x, f1.y);
                }
                ((uint2*)Abase)[smi] = v;
            }
        }
        asm volatile("bar.sync %0, 128;" :: "r"(1 + gid) : "memory");

        int cur = 0;
        while (blk < KVB) {
            const int nxt = blk + KVC;
            uint2 stg[4];
            if (nxt < KVB) {
                const int srow = nxt * 64 + gid * 16;
#pragma unroll
                for (int e = 0; e < 4; e++) {
                    int row, smi, gof;
                    decode(e, row, smi, gof);
                    stg[e] = make_uint2(0u, 0u);
                    if (srow + row < NA) {
                        const float* p = hA + (size_t)srow * HID + gof;
                        const float2 f0 = *(const float2*)p;
                        const float2 f1 = *(const float2*)(p + 8);
                        stg[e].x = ph2(f0.x, f0.y);
                        stg[e].y = ph2(f1.x, f1.y);
                    }
                }
            }

            float d[8][4];
#pragma unroll
            for (int i = 0; i < 8; i++)
#pragma unroll
                for (int j = 0; j < 4; j++) d[i][j] = 0.f;

            gemm_frag((const uint2*)(Abase + cur * 1024), 16,
                      (const uint2*)(U + sel * 8192), 0, d, 0, colh, g, tig);

            const int brow = blk * 64 + gid * 16;
#pragma unroll
            for (int half = 0; half < 2; half++) {
                const int row = brow + g + half * 8;
                if (row < NA) {
#pragma unroll
                    for (int nt = 0; nt < 8; nt++) {
                        const int col = colh * 64 + nt * 8 + 2 * tig;
                        *(unsigned*)&Cp[(size_t)row * HID + col] =
                            ph2(d[nt][half * 2 + 0], d[nt][half * 2 + 1]);
                    }
                }
            }

            if (nxt < KVB) {
                unsigned* A1 = Abase + (cur ^ 1) * 1024;
#pragma unroll
                for (int e = 0; e < 4; e++) {
                    int row, smi, gof;
                    decode(e, row, smi, gof);
                    ((uint2*)A1)[smi] = stg[e];
                }
            }
            asm volatile("bar.sync %0, 128;" :: "r"(1 + gid) : "memory");
            blk = nxt;
            cur ^= 1;
        }
    } else {
        pack_frags(Wq, U, 0, 128, 1 << 30, HID, 3, tid, 512);

        const int mrow = (warp >> 1) * 16;
        const int colh = warp & 1;

        for (int blk = (int)blockIdx.x - KVC; blk < QBL; blk += QC) {
            const int brow = blk * 128;
            pack_frags(hQ, U + 8192, brow, 128, NQ, HID, 3, tid, 512);
            __syncthreads();

            float d[8][4];
#pragma unroll
            for (int i = 0; i < 8; i++)
#pragma unroll
                for (int j = 0; j < 4; j++) d[i][j] = 0.f;

            gemm_frag((const uint2*)(U + 8192), 128,
                      (const uint2*)U, 0, d, mrow, colh, g, tig);

#pragma unroll
            for (int half = 0; half < 2; half++) {
                const int row = brow + mrow + g + half * 8;
                if (row >= NQ) continue;
#pragma unroll
                for (int nt = 0; nt < 8; nt++) {
                    const int col = colh * 64 + nt * 8 + 2 * tig;
                    *(unsigned*)&Cq[(size_t)row * HID + col] =
                        ph2(d[nt][half * 2 + 0], d[nt][half * 2 + 1]);
                }
            }
            __syncthreads();
        }
    }
}

// ---------------------------------------------------------------------------
// mlp_fused (unchanged R15: prepacked-weight copies)
// ---------------------------------------------------------------------------
__global__ __launch_bounds__(512, 2) void mlp_fused(
    const float* __restrict__ hQ, const float* __restrict__ agg,
    const unsigned* __restrict__ W1f, const float* __restrict__ b1,
    const unsigned* __restrict__ W2f, const float* __restrict__ b2,
    const float* __restrict__ gamma, const float* __restrict__ beta,
    float* __restrict__ out)
{
    extern __shared__ unsigned U[];
    __shared__ float2 scr[256];
    unsigned* AU = U + 16384;

    const int tid  = threadIdx.x;
    const int warp = tid >> 5;
    const int lane = tid & 31;
    const int g    = lane >> 2;
    const int tig  = lane & 3;
    const int mrow = (warp >> 1) * 16;
    const int colh = warp & 1;
    const int brow = blockIdx.x * 128;

    float d[8][4];
#pragma unroll
    for (int i = 0; i < 8; i++)
#pragma unroll
        for (int j = 0; j < 4; j++) d[i][j] = 0.f;

    {
        const uint4* src = (const uint4*)W1f;
        uint4* dst = (uint4*)U;
#pragma unroll
        for (int i = 0; i < 8; i++) dst[tid + i * 512] = src[tid + i * 512];
    }
    pack_frags(hQ, AU, brow, 128, NQ, HID, 3, tid, 512);
    __syncthreads();
    gemm_frag((const uint2*)AU, 128, (const uint2*)U, 0, d, mrow, colh, g, tig);
    __syncthreads();
    pack_frags(agg, AU, brow, 128, NQ, HID, 3, tid, 512);
    __syncthreads();
    gemm_frag((const uint2*)AU, 128, (const uint2*)U, 8, d, mrow, colh, g, tig);
    __syncthreads();

#pragma unroll
    for (int half = 0; half < 2; half++) {
        const int rl = mrow + g + half * 8;
#pragma unroll
        for (int nt = 0; nt < 8; nt++) {
            const int col = colh * 64 + nt * 8 + 2 * tig;
            const float2 bi = *(const float2*)&b1[col];
            const float x0 = fmaxf(d[nt][half * 2 + 0] + bi.x, 0.f);
            const float x1 = fmaxf(d[nt][half * 2 + 1] + bi.y, 0.f);
            const int chunk = colh * 4 + (nt >> 1);
            AU[((chunk * 128 + rl) * 4 + tig) * 2 + (nt & 1)] = ph2(x0, x1);
        }
    }
    {
        const uint4* src = (const uint4*)W2f;
        uint4* dst = (uint4*)U;
#pragma unroll
        for (int i = 0; i < 4; i++) dst[tid + i * 512] = src[tid + i * 512];
    }
    __syncthreads();

#pragma unroll
    for (int i = 0; i < 8; i++)
#pragma unroll
        for (int j = 0; j < 4; j++) d[i][j] = 0.f;
    gemm_frag((const uint2*)AU, 128, (const uint2*)U, 0, d, mrow, colh, g, tig);

    float psum[2], psq[2];
#pragma unroll
    for (int half = 0; half < 2; half++) {
        const int  row = brow + mrow + g + half * 8;
        const bool ok  = row < NQ;
        float s = 0.f, ss = 0.f;
#pragma unroll
        for (int nt = 0; nt < 8; nt++) {
            const int col = colh * 64 + nt * 8 + 2 * tig;
            const float2 bi = *(const float2*)&b2[col];
            float x0 = d[nt][half * 2 + 0] + bi.x;
            float x1 = d[nt][half * 2 + 1] + bi.y;
            if (ok) {
                const float2 rr = *(const float2*)&hQ[(size_t)row * HID + col];
                x0 += rr.x; x1 += rr.y;
            }
            d[nt][half * 2 + 0] = x0;
            d[nt][half * 2 + 1] = x1;
            s  += x0 + x1;
            ss += x0 * x0 + x1 * x1;
        }
        s  += __shfl_xor_sync(0xffffffffu, s, 1);
        s  += __shfl_xor_sync(0xffffffffu, s, 2);
        ss += __shfl_xor_sync(0xffffffffu, ss, 1);
        ss += __shfl_xor_sync(0xffffffffu, ss, 2);
        psum[half] = s; psq[half] = ss;
    }
#pragma unroll
    for (int half = 0; half < 2; half++) {
        const int rl = mrow + g + half * 8;
        if (tig == 0) scr[rl * 2 + colh] = make_float2(psum[half], psq[half]);
    }
    __syncthreads();
#pragma unroll
    for (int half = 0; half < 2; half++) {
        const int rl  = mrow + g + half * 8;
        const int row = brow + rl;
        const float2 f0 = scr[rl * 2 + 0];
        const float2 f1 = scr[rl * 2 + 1];
        const float mean = (f0.x + f1.x) * (1.f / 128.f);
        const float inv  = rsqrtf((f0.y + f1.y) * (1.f / 128.f)
                                  - mean * mean + 1e-5f);
        if (row >= NQ) continue;
#pragma unroll
        for (int nt = 0; nt < 8; nt++) {
            const int col = colh * 64 + nt * 8 + 2 * tig;
            const float2 gg = *(const float2*)&gamma[col];
            const float2 bb = *(const float2*)&beta[col];
            float2 o;
            o.x = (d[nt][half * 2 + 0] - mean) * inv * gg.x + bb.x;
            o.y = (d[nt][half * 2 + 1] - mean) * inv * gg.y + bb.y;
            *(float2*)&out[(size_t)row * HID + col] = o;
        }
    }
}

// ---------------------------------------------------------------------------
// Attention v2 (R13, the 146us config): one warp per query; shuffle-free
// score phase; Q now read as fp16.
// ---------------------------------------------------------------------------
__global__ __launch_bounds__(256) void attn_kernel(
    const __half* __restrict__ Qq, const __half* __restrict__ Ka,
    const __half* __restrict__ Va, const float* __restrict__ edge_attr,
    const int*   __restrict__ src_idx, const float* __restrict__ W_rbf,
    float* __restrict__ agg)
{
    __shared__ float  s_al[8][8 * 36];
    __shared__ int    s_src[8][32];
    __shared__ float4 s_ea[8][128];

    const int warp = threadIdx.x >> 5;
    const int lane = threadIdx.x & 31;
    const int q   = blockIdx.x * 8 + warp;
    const int h   = lane >> 2;
    const int sm4 = lane & 3;

    s_src[warp][lane] = src_idx[(size_t)q * KNN + lane];
    {
        const float4* ea4 = (const float4*)(edge_attr + (size_t)q * KNN * E_F);
#pragma unroll
        for (int t = 0; t < 4; t++)
            s_ea[warp][lane + 32 * t] = ea4[lane + 32 * t];
    }

    float qv[16], wr[16];
    {
        const uint4 q0 = *(const uint4*)(Qq + (size_t)q * HID + h * 16);
        const uint4 q1 = *(const uint4*)(Qq + (size_t)q * HID + h * 16 + 8);
        const __half2* qh0 = (const __half2*)&q0;
        const __half2* qh1 = (const __half2*)&q1;
#pragma unroll
        for (int i = 0; i < 4; i++) {
            const float2 f0 = __half22float2(qh0[i]);
            qv[i * 2 + 0] = f0.x; qv[i * 2 + 1] = f0.y;
            const float2 f1 = __half22float2(qh1[i]);
            qv[8 + i * 2 + 0] = f1.x; qv[8 + i * 2 + 1] = f1.y;
        }
        const float4* wp = (const float4*)(W_rbf + h * E_F);
#pragma unroll
        for (int i = 0; i < 4; i++) {
            float4 b = wp[i];
            wr[i * 4 + 0] = b.x; wr[i * 4 + 1] = b.y;
            wr[i * 4 + 2] = b.z; wr[i * 4 + 3] = b.w;
        }
    }
    __syncwarp();

    float sc[8];
#pragma unroll
    for (int t = 0; t < 8; t++) {
        const int j  = sm4 + 4 * t;
        const int sj = s_src[warp][j];
        const uint4 k0 = *(const uint4*)(Ka + (size_t)sj * HID + h * 16);
        const uint4 k1 = *(const uint4*)(Ka + (size_t)sj * HID + h * 16 + 8);
        float dd = 0.f;
        {
            const __half2* kh = (const __half2*)&k0;
#pragma unroll
            for (int i = 0; i < 4; i++) {
                const float2 f = __half22float2(kh[i]);
                dd = fmaf(qv[i * 2 + 0], f.x, dd);
                dd = fmaf(qv[i * 2 + 1], f.y, dd);
            }
            const __half2* kh1 = (const __half2*)&k1;
#pragma unroll
            for (int i = 0; i < 4; i++) {
                const float2 f = __half22float2(kh1[i]);
                dd = fmaf(qv[8 + i * 2 + 0], f.x, dd);
                dd = fmaf(qv[8 + i * 2 + 1], f.y, dd);
            }
        }
        float rr = 0.f;
#pragma unroll
        for (int c = 0; c < 4; c++) {
            const float4 e = s_ea[warp][j * 4 + c];
            rr = fmaf(e.x, wr[c * 4 + 0], rr);
            rr = fmaf(e.y, wr[c * 4 + 1], rr);
            rr = fmaf(e.z, wr[c * 4 + 2], rr);
            rr = fmaf(e.w, wr[c * 4 + 3], rr);
        }
        sc[t] = dd * 0.25f + rr;
    }

    float m = sc[0];
#pragma unroll
    for (int t = 1; t < 8; t++) m = fmaxf(m, sc[t]);
    m = fmaxf(m, __shfl_xor_sync(0xffffffffu, m, 1));
    m = fmaxf(m, __shfl_xor_sync(0xffffffffu, m, 2));
    float sum = 0.f;
#pragma unroll
    for (int t = 0; t < 8; t++) { sc[t] = __expf(sc[t] - m); sum += sc[t]; }
    sum += __shfl_xor_sync(0xffffffffu, sum, 1);
    sum += __shfl_xor_sync(0xffffffffu, sum, 2);
    const float inv = 1.f / (sum + 1e-16f);
#pragma unroll
    for (int t = 0; t < 8; t++)
        s_al[warp][h * 36 + sm4 + 4 * t] = sc[t] * inv;
    __syncwarp();

    float4 acc = make_float4(0.f, 0.f, 0.f, 0.f);
#pragma unroll
    for (int j = 0; j < KNN; j++) {
        const float a  = s_al[warp][h * 36 + j];
        const int   sj = s_src[warp][j];
        const __half2* vr = (const __half2*)(Va + (size_t)sj * HID);
        const float2 v01 = __half22float2(vr[lane * 2 + 0]);
        const float2 v23 = __half22float2(vr[lane * 2 + 1]);
        acc.x = fmaf(a, v01.x, acc.x);
        acc.y = fmaf(a, v01.y, acc.y);
        acc.z = fmaf(a, v23.x, acc.z);
        acc.w = fmaf(a, v23.y, acc.w);
    }
    *(float4*)&agg[(size_t)q * HID + lane * 4] = acc;
}

// ---------------------------------------------------------------------------
extern "C" void kernel_launch(void* const* d_in, const int* in_sizes, int n_in,
                              void* d_out, int out_size)
{
    const float* h_atom    = (const float*)d_in[0];
    const float* h_query   = (const float*)d_in[1];
    const float* edge_attr = (const float*)d_in[2];
    const float* W_q       = (const float*)d_in[3];
    const float* W_k       = (const float*)d_in[4];
    const float* W_v       = (const float*)d_in[5];
    const float* W_rbf     = (const float*)d_in[6];
    const float* W1        = (const float*)d_in[7];
    const float* b1        = (const float*)d_in[8];
    const float* W2        = (const float*)d_in[9];
    const float* b2        = (const float*)d_in[10];
    const float* ln_gamma  = (const float*)d_in[11];
    const float* ln_beta   = (const float*)d_in[12];
    const int*   edge_index= (const int*)  d_in[13];   // [2,E]; row0 = src
    float* out = (float*)d_out;

    float *agg;
    __half *Qq, *Ka, *Va;
    unsigned *W1f, *W2f;
    cudaGetSymbolAddress((void**)&Qq,  g_Qq);
    cudaGetSymbolAddress((void**)&Ka,  g_Ka);
    cudaGetSymbolAddress((void**)&Va,  g_Va);
    cudaGetSymbolAddress((void**)&agg, g_agg);
    cudaGetSymbolAddress((void**)&W1f, g_W1f);
    cudaGetSymbolAddress((void**)&W2f, g_W2f);

    cudaFuncSetAttribute(proj_all,
                         cudaFuncAttributeMaxDynamicSharedMemorySize, 98304);
    cudaFuncSetAttribute(mlp_fused,
                         cudaFuncAttributeMaxDynamicSharedMemorySize, 98304);

    // persistent Q+K+V projections + W1/W2 fragment prepack (2 extra blocks)
    proj_all<<<KVC + QC + 2, 512, 98304>>>(h_atom, h_query, W_k, W_v, W_q,
                                           W1, W2, W1f, W2f, Ka, Va, Qq);

    // segment-softmax attention + aggregation (shuffle-free score phase)
    attn_kernel<<<NQ / 8, 256>>>(Qq, Ka, Va, edge_attr, edge_index, W_rbf, agg);

    // fused MLP1 + ReLU + MLP2 + residual + LayerNorm (prepacked weights)
    mlp_fused<<<MLPB, 512, 98304>>>(h_query, agg, W1f, b1, W2f, b2,
                                    ln_gamma, ln_beta, out);
}